// round 14
// baseline (speedup 1.0000x reference)
#include <cuda_runtime.h>
#include <cuda_bf16.h>
#include <mma.h>
#include <math.h>

using namespace nvcuda;

#define BB   32
#define TT   512
#define LAT  256
#define HID  1024
#define HO   512
#define G3   1536
#define MTOT (BB*TT)

// GRU partitioning: 4 groups x 8 batches; 64 CTAs, each serves TWO groups
// (pair p = groups 2p, 2p+1) with the SAME register-resident W fragments.
#define NG   4
#define CPG  32
#define BPG  8
#define JPC  16
#define GROWS 48
#define RROW 10
#define RMT  160

#define GLDA 40          // bf16 elems per smem row in gemm (32 data + 8 pad = 80B)

// ---------------- scratch (device globals; no allocations allowed) ----------
__device__ float g_fc[BB*HID];
__device__ float g_gx[(size_t)MTOT*G3];
__device__ __nv_bfloat16 g_ahi[(size_t)MTOT*HID];   // A operand hi
__device__ __nv_bfloat16 g_alo[(size_t)MTOT*HID];   // A operand lo
__device__ __nv_bfloat16 g_whi[(size_t)G3*HID];     // W operand hi (re-split per layer)
__device__ __nv_bfloat16 g_wlo[(size_t)G3*HID];
// stamped hidden state: low 32 = packed bf16 (hi | lo<<16), high 32 = stamp
__device__ unsigned long long g_hs[NG][2][BPG*HO];
__device__ unsigned int g_epoch[2][CPG][8];         // per pair-set CTA stamp base

// fast gates (MUFU): rel err ~1e-6, budget 1e-3
__device__ __forceinline__ float sigf(float x) {
    return __fdividef(1.0f, 1.0f + __expf(-x));
}
__device__ __forceinline__ float tanhfast(float x) {
    return 2.0f * __fdividef(1.0f, 1.0f + __expf(-2.0f * x)) - 1.0f;
}

__device__ __forceinline__ void split1(float x, __nv_bfloat16& hi, __nv_bfloat16& lo) {
    hi = __float2bfloat16(x);
    lo = __float2bfloat16(x - __bfloat162float(hi));
}
__device__ __forceinline__ void split2(float x, float y, unsigned& hi, unsigned& lo) {
    __nv_bfloat16 hx, lx, hy, ly;
    split1(x, hx, lx); split1(y, hy, ly);
    __nv_bfloat162 h2 = __halves2bfloat162(hx, hy);
    __nv_bfloat162 l2 = __halves2bfloat162(lx, ly);
    hi = *reinterpret_cast<unsigned*>(&h2);
    lo = *reinterpret_cast<unsigned*>(&l2);
}
__device__ __forceinline__ unsigned prmtb(unsigned a, unsigned b, unsigned sel) {
    unsigned d;
    asm("prmt.b32 %0, %1, %2, %3;" : "=r"(d) : "r"(a), "r"(b), "r"(sel));
    return d;
}

// mma.m16n8k16 row.col f32 += bf16 * bf16
__device__ __forceinline__ void mma_bf16(float d[4], const unsigned a[4],
                                         unsigned b0, unsigned b1) {
    asm volatile(
        "mma.sync.aligned.m16n8k16.row.col.f32.bf16.bf16.f32 "
        "{%0,%1,%2,%3}, {%4,%5,%6,%7}, {%8,%9}, {%0,%1,%2,%3};"
        : "+f"(d[0]), "+f"(d[1]), "+f"(d[2]), "+f"(d[3])
        : "r"(a[0]), "r"(a[1]), "r"(a[2]), "r"(a[3]), "r"(b0), "r"(b1));
}

// ---------------- FC + ReLU --------------------------------------------------
__global__ void fc_kernel(const float* __restrict__ z,
                          const float* __restrict__ fc_w,
                          const float* __restrict__ fc_b) {
    __shared__ float zs[LAT];
    int b = blockIdx.x;
    zs[threadIdx.x] = z[b*LAT + threadIdx.x];
    __syncthreads();
    for (int h = threadIdx.x; h < HID; h += blockDim.x) {
        const float4* w = (const float4*)(fc_w + (size_t)h*LAT);
        float s = fc_b[h];
        #pragma unroll 8
        for (int k = 0; k < LAT/4; k++) {
            float4 wv = w[k];
            float4 zv = *(const float4*)(zs + 4*k);
            s += wv.x*zv.x + wv.y*zv.y + wv.z*zv.z + wv.w*zv.w;
        }
        g_fc[b*HID + h] = fmaxf(s, 0.0f);
    }
}

// ---------------- split prepasses -------------------------------------------
__global__ void split_w(const float* __restrict__ W, int n) {
    int i = (blockIdx.x*256 + threadIdx.x)*4;
    if (i >= n) return;
    float4 v = *(const float4*)(W + i);
    __nv_bfloat16 h0,l0,h1,l1,h2,l2,h3,l3;
    split1(v.x,h0,l0); split1(v.y,h1,l1); split1(v.z,h2,l2); split1(v.w,h3,l3);
    *(__nv_bfloat162*)(g_whi + i)     = __halves2bfloat162(h0,h1);
    *(__nv_bfloat162*)(g_whi + i + 2) = __halves2bfloat162(h2,h3);
    *(__nv_bfloat162*)(g_wlo + i)     = __halves2bfloat162(l0,l1);
    *(__nv_bfloat162*)(g_wlo + i + 2) = __halves2bfloat162(l2,l3);
}

__global__ void split_a0(const float* __restrict__ chord) {
    size_t i = ((size_t)blockIdx.x*256 + threadIdx.x)*4;
    int m = (int)(i >> 10);
    int k = (int)(i & (HID-1));
    int b = m >> 9;
    float4 f = *(const float4*)(g_fc + (size_t)b*HID + k);
    float4 c = *(const float4*)(chord + i);
    float a0 = f.x + 0.01f*c.x, a1 = f.y + 0.01f*c.y;
    float a2 = f.z + 0.01f*c.z, a3 = f.w + 0.01f*c.w;
    __nv_bfloat16 h0,l0,h1,l1,h2,l2,h3,l3;
    split1(a0,h0,l0); split1(a1,h1,l1); split1(a2,h2,l2); split1(a3,h3,l3);
    *(__nv_bfloat162*)(g_ahi + i)     = __halves2bfloat162(h0,h1);
    *(__nv_bfloat162*)(g_ahi + i + 2) = __halves2bfloat162(h2,h3);
    *(__nv_bfloat162*)(g_alo + i)     = __halves2bfloat162(l0,l1);
    *(__nv_bfloat162*)(g_alo + i + 2) = __halves2bfloat162(l2,l3);
}

// ---------------- Input projection GEMM (R11 128x128 config, known-good) -----
template<int K>
__global__ void __launch_bounds__(256, 2) gemm_bf16(const float* __restrict__ bias) {
    extern __shared__ __align__(16) __nv_bfloat16 ts[];   // [2][4][128][GLDA]
    int bm = blockIdx.y*128, bn = blockIdx.x*128;
    int tid = threadIdx.x, lane = tid & 31, wid = tid >> 5;
    int wm = wid >> 1, wn = wid & 1;

    unsigned sb = (unsigned)__cvta_generic_to_shared(ts);

    auto issue_stage = [&](int k0, int buf) {
        #pragma unroll
        for (int c = 0; c < 8; c++) {
            int chunk = tid + c*256;
            int op = chunk >> 9;
            int r = (chunk >> 2) & 127;
            int seg = chunk & 3;
            const __nv_bfloat16* gp;
            if (op == 0)      gp = g_ahi + (size_t)(bm + r)*K + k0 + seg*8;
            else if (op == 1) gp = g_alo + (size_t)(bm + r)*K + k0 + seg*8;
            else if (op == 2) gp = g_whi + (size_t)(bn + r)*K + k0 + seg*8;
            else              gp = g_wlo + (size_t)(bn + r)*K + k0 + seg*8;
            unsigned dst = sb + (((buf*4 + op)*128 + r)*GLDA + seg*8)*2;
            asm volatile("cp.async.cg.shared.global [%0], [%1], 16;"
                         :: "r"(dst), "l"(gp));
        }
        asm volatile("cp.async.commit_group;");
    };
    auto plane = [&](int buf, int op) -> const __nv_bfloat16* {
        return ts + (size_t)((buf*4 + op)*128)*GLDA;
    };

    wmma::fragment<wmma::accumulator,16,16,16,float> acc[2][4];
    #pragma unroll
    for (int i = 0; i < 2; i++)
        #pragma unroll
        for (int j = 0; j < 4; j++) wmma::fill_fragment(acc[i][j], 0.0f);

    issue_stage(0, 0);
    int buf = 0;
    constexpr int S = K/32;
    for (int s = 0; s < S; s++) {
        if (s + 1 < S) {
            issue_stage((s+1)*32, buf ^ 1);
            asm volatile("cp.async.wait_group 1;");
        } else {
            asm volatile("cp.async.wait_group 0;");
        }
        __syncthreads();
        #pragma unroll
        for (int kk = 0; kk < 32; kk += 16) {
            wmma::fragment<wmma::matrix_a,16,16,16,__nv_bfloat16,wmma::row_major> fa_h[2], fa_l[2];
            #pragma unroll
            for (int i = 0; i < 2; i++) {
                wmma::load_matrix_sync(fa_h[i], plane(buf,0) + (wm*32 + i*16)*GLDA + kk, GLDA);
                wmma::load_matrix_sync(fa_l[i], plane(buf,1) + (wm*32 + i*16)*GLDA + kk, GLDA);
            }
            #pragma unroll
            for (int j = 0; j < 4; j++) {
                wmma::fragment<wmma::matrix_b,16,16,16,__nv_bfloat16,wmma::col_major> fb_h, fb_l;
                wmma::load_matrix_sync(fb_h, plane(buf,2) + (wn*64 + j*16)*GLDA + kk, GLDA);
                wmma::load_matrix_sync(fb_l, plane(buf,3) + (wn*64 + j*16)*GLDA + kk, GLDA);
                #pragma unroll
                for (int i = 0; i < 2; i++) {
                    wmma::mma_sync(acc[i][j], fa_h[i], fb_h, acc[i][j]);
                    wmma::mma_sync(acc[i][j], fa_h[i], fb_l, acc[i][j]);
                    wmma::mma_sync(acc[i][j], fa_l[i], fb_h, acc[i][j]);
                }
            }
        }
        __syncthreads();
        buf ^= 1;
    }

    float* scratch = reinterpret_cast<float*>(ts) + wid*320;
    #pragma unroll
    for (int i = 0; i < 2; i++)
        #pragma unroll
        for (int j = 0; j < 4; j++) {
            wmma::store_matrix_sync(scratch, acc[i][j], 20, wmma::mem_row_major);
            __syncwarp();
            int r = lane >> 1, cb = (lane & 1)*8;
            int row = bm + wm*32 + i*16 + r;
            int col = bn + wn*64 + j*16 + cb;
            float4 v0 = *(float4*)&scratch[r*20 + cb];
            float4 v1 = *(float4*)&scratch[r*20 + cb + 4];
            const float* bp = bias + col;
            float* gp = g_gx + (size_t)row*G3 + col;
            *(float4*)gp = make_float4(v0.x + bp[0], v0.y + bp[1], v0.z + bp[2], v0.w + bp[3]);
            *(float4*)(gp + 4) = make_float4(v1.x + bp[4], v1.y + bp[5], v1.z + bp[6], v1.w + bp[7]);
            __syncwarp();
        }
}

// ---------------- Persistent GRU: dual-group interleaved, stamped exchange ---
// 64 CTAs. CTA (pair p, cig) owns j-slice [cig*16, cig*16+16) in BOTH groups
// 2p and 2p+1 (same layer weights -> same W fragments, zero extra W regs).
// Each timestep: phase A (group 2p) then phase B (group 2p+1). While a CTA
// computes one phase, the other group's published stamps propagate through L2,
// hiding the exchange latency that dominated the single-group version.
// red WAR safety: phase X's red slot is re-written only after the next
// phase-X barrier, which orders it after all gate reads of the previous step
// (reads precede the other phase's barrier; writes follow it).
__global__ void __launch_bounds__(256) gru7(const float* __restrict__ whh,
                                            const float* __restrict__ bhh,
                                            float* __restrict__ dout,
                                            const int* __restrict__ seq_lens,
                                            int dst_mode) {
    __shared__ float red[2][24*RMT];
    __shared__ float bh_sm[GROWS];

    int tid = threadIdx.x, lane = tid & 31, warp = tid >> 5;
    int pair = blockIdx.x >> 5;           // 0 or 1
    int cig = blockIdx.x & 31;
    int jbase = cig * JPC;
    int gA = pair*2, gB = pair*2 + 1;

    unsigned base = g_epoch[pair][cig][0];

    // preload W fragments into registers (split-bf16 hi/lo) — shared by A and B
    unsigned awhi[3][4][4], awlo[3][4][4];
    {
        int r = lane >> 2, c = (lane & 3)*2;
        #pragma unroll
        for (int m = 0; m < 3; m++) {
            size_t row0 = (size_t)(m*HO + jbase + r)*HO;
            size_t row1 = row0 + 8*(size_t)HO;
            #pragma unroll
            for (int kt4 = 0; kt4 < 4; kt4++) {
                int kb = (warp*4 + kt4)*16 + c;
                float2 w00 = *(const float2*)(whh + row0 + kb);
                float2 w10 = *(const float2*)(whh + row1 + kb);
                float2 w01 = *(const float2*)(whh + row0 + kb + 8);
                float2 w11 = *(const float2*)(whh + row1 + kb + 8);
                split2(w00.x, w00.y, awhi[m][kt4][0], awlo[m][kt4][0]);
                split2(w10.x, w10.y, awhi[m][kt4][1], awlo[m][kt4][1]);
                split2(w01.x, w01.y, awhi[m][kt4][2], awlo[m][kt4][2]);
                split2(w11.x, w11.y, awhi[m][kt4][3], awlo[m][kt4][3]);
            }
        }
    }
    if (tid < GROWS) bh_sm[tid] = bhh[(tid >> 4)*HO + jbase + (tid & 15)];

    const int gjj = tid & 15, gb = tid >> 4;
    const int bA = gA*BPG + gb, bB = gB*BPG + gb;
    int slenA = TT, slenB = TT;
    if (dst_mode == 2 && tid < 128) {
        slenA = seq_lens[bA];
        slenB = seq_lens[bB];
    }

    float gxA[3] = {0.f,0.f,0.f}, gxB[3] = {0.f,0.f,0.f};
    if (tid < 128) {
        size_t ba = (size_t)bA*TT*G3 + jbase + gjj;
        size_t bb = (size_t)bB*TT*G3 + jbase + gjj;
        gxA[0] = g_gx[ba]; gxA[1] = g_gx[ba + HO]; gxA[2] = g_gx[ba + 2*HO];
        gxB[0] = g_gx[bb]; gxB[1] = g_gx[bb + HO]; gxB[2] = g_gx[bb + 2*HO];
    }
    float hpA = 0.0f, hpB = 0.0f;
    __syncthreads();

    const int bq = lane >> 2;             // B-frag batch index
    const int kc2 = (lane & 3)*2;         // B-frag k offset

    // one phase of one group's recurrence at step t
    auto phase = [&](int grp, int rslot, float& h_prev, float* gx,
                     int slen, int b_glob, int t) {
        // ---- obtain h(t): poll stamped words (t>0) or zeros ----
        unsigned long long w[4][4];
        if (t == 0) {
            #pragma unroll
            for (int a = 0; a < 4; a++)
                #pragma unroll
                for (int e = 0; e < 4; e++) w[a][e] = 0ull;
        } else {
            const unsigned tgt = base + (unsigned)t;
            const unsigned long long* hb = g_hs[grp][t & 1] + bq*HO;
            bool ok;
            do {
                ok = true;
                #pragma unroll
                for (int kt4 = 0; kt4 < 4; kt4++) {
                    int kb = (warp*4 + kt4)*16 + kc2;
                    const unsigned long long* p = hb + kb;
                    asm volatile("ld.relaxed.gpu.global.u64 %0, [%1];" : "=l"(w[kt4][0]) : "l"(p));
                    asm volatile("ld.relaxed.gpu.global.u64 %0, [%1];" : "=l"(w[kt4][1]) : "l"(p + 1));
                    asm volatile("ld.relaxed.gpu.global.u64 %0, [%1];" : "=l"(w[kt4][2]) : "l"(p + 8));
                    asm volatile("ld.relaxed.gpu.global.u64 %0, [%1];" : "=l"(w[kt4][3]) : "l"(p + 9));
                    #pragma unroll
                    for (int e = 0; e < 4; e++)
                        ok &= ((unsigned)(w[kt4][e] >> 32) == tgt);
                }
            } while (__ballot_sync(0xffffffffu, !ok));
        }

        // ---- tensor-core GEMV ----
        float d[3][4];
        #pragma unroll
        for (int m = 0; m < 3; m++)
            #pragma unroll
            for (int e = 0; e < 4; e++) d[m][e] = 0.0f;

        #pragma unroll
        for (int kt4 = 0; kt4 < 4; kt4++) {
            unsigned p0 = (unsigned)w[kt4][0], p1 = (unsigned)w[kt4][1];
            unsigned p2 = (unsigned)w[kt4][2], p3 = (unsigned)w[kt4][3];
            unsigned bh0 = prmtb(p0, p1, 0x5410), bl0 = prmtb(p0, p1, 0x7632);
            unsigned bh1 = prmtb(p2, p3, 0x5410), bl1 = prmtb(p2, p3, 0x7632);
            #pragma unroll
            for (int m = 0; m < 3; m++) {
                mma_bf16(d[m], awhi[m][kt4], bh0, bh1);
                mma_bf16(d[m], awhi[m][kt4], bl0, bl1);
                mma_bf16(d[m], awlo[m][kt4], bh0, bh1);
            }
        }
        {
            float* rb = red[rslot];
            #pragma unroll
            for (int m = 0; m < 3; m++) {
                float* rp = rb + (warp*3 + m)*RMT + (lane>>2)*RROW + (lane&3)*2;
                *(float2*)rp            = make_float2(d[m][0], d[m][1]);
                *(float2*)(rp + 8*RROW) = make_float2(d[m][2], d[m][3]);
            }
        }
        __syncthreads();

        // ---- fused reduce + gate math + publish (tid<128) ----
        if (tid < 128) {
            const float* rb = red[rslot];
            float gh[3];
            #pragma unroll
            for (int g = 0; g < 3; g++) {
                const float* rp = rb + g*RMT + gjj*RROW + gb;
                float s = 0.0f;
                #pragma unroll
                for (int w8 = 0; w8 < 8; w8++)
                    s += rp[w8*3*RMT];
                gh[g] = s + bh_sm[g*16 + gjj];
            }
            float r  = sigf(gx[0] + gh[0]);
            float zg = sigf(gx[1] + gh[1]);
            float n  = tanhfast(gx[2] + r*gh[2]);
            float hn2 = (1.0f - zg)*n + zg*h_prev;
            h_prev = hn2;

            __nv_bfloat16 hi, lo;
            split1(hn2, hi, lo);
            unsigned pk = (unsigned)*reinterpret_cast<unsigned short*>(&hi)
                        | ((unsigned)*reinterpret_cast<unsigned short*>(&lo) << 16);

            if (t < TT - 1) {
                unsigned long long word =
                    ((unsigned long long)(base + (unsigned)(t + 1)) << 32) | pk;
                unsigned long long* hp = &g_hs[grp][(t + 1) & 1][gb*HO + jbase + gjj];
                asm volatile("st.relaxed.gpu.global.u64 [%0], %1;" :: "l"(hp), "l"(word));
            }
            size_t idx = ((size_t)b_glob*TT + t)*HO + jbase + gjj;
            if (dst_mode == 2) {
                dout[idx] = (t < slen) ? hn2 : 0.0f;
            } else {
                g_ahi[idx] = hi;
                g_alo[idx] = lo;
            }
            if (t < TT - 1) {
                size_t bse = ((size_t)b_glob*TT + (t + 1))*G3 + jbase + gjj;
                gx[0] = g_gx[bse];
                gx[1] = g_gx[bse + HO];
                gx[2] = g_gx[bse + 2*HO];
            }
        }
    };

    for (int t = 0; t < TT; t++) {
        phase(gA, 0, hpA, gxA, slenA, bA, t);   // B's stamps propagate meanwhile
        phase(gB, 1, hpB, gxB, slenB, bB, t);   // A's stamps propagate meanwhile
    }
    if (tid == 0) g_epoch[pair][cig][0] = base + TT;
}

// ---------------- launch ----------------------------------------------------
#define GEMM_SMEM (2*4*128*GLDA*2)

extern "C" void kernel_launch(void* const* d_in, const int* in_sizes, int n_in,
                              void* d_out, int out_size) {
    const float* z     = (const float*)d_in[0];
    const int*   seq   = (const int*)  d_in[1];
    const float* chord = (const float*)d_in[2];
    const float* fc_w  = (const float*)d_in[3];
    const float* fc_b  = (const float*)d_in[4];
    const float* w_ih0 = (const float*)d_in[5];
    const float* w_hh0 = (const float*)d_in[6];
    const float* b_ih0 = (const float*)d_in[7];
    const float* b_hh0 = (const float*)d_in[8];
    const float* w_ih1 = (const float*)d_in[9];
    const float* w_hh1 = (const float*)d_in[10];
    const float* b_ih1 = (const float*)d_in[11];
    const float* b_hh1 = (const float*)d_in[12];
    const float* w_ih2 = (const float*)d_in[13];
    const float* w_hh2 = (const float*)d_in[14];
    const float* b_ih2 = (const float*)d_in[15];
    const float* b_hh2 = (const float*)d_in[16];
    float* out = (float*)d_out;

    cudaFuncSetAttribute(gemm_bf16<HID>, cudaFuncAttributeMaxDynamicSharedMemorySize, GEMM_SMEM);
    cudaFuncSetAttribute(gemm_bf16<HO>,  cudaFuncAttributeMaxDynamicSharedMemorySize, GEMM_SMEM);

    dim3 ggrid(G3/128, MTOT/128);   // (12, 128)

    fc_kernel<<<BB, LAT>>>(z, fc_w, fc_b);
    split_a0<<<(int)(((size_t)MTOT*HID)/1024), 256>>>(chord);

    split_w<<<(G3*HID)/1024, 256>>>(w_ih0, G3*HID);
    gemm_bf16<HID><<<ggrid, 256, GEMM_SMEM>>>(b_ih0);
    gru7<<<64, 256>>>(w_hh0, b_hh0, nullptr, seq, 0);

    split_w<<<(G3*HO)/1024, 256>>>(w_ih1, G3*HO);
    gemm_bf16<HO><<<ggrid, 256, GEMM_SMEM>>>(b_ih1);
    gru7<<<64, 256>>>(w_hh1, b_hh1, nullptr, seq, 1);

    split_w<<<(G3*HO)/1024, 256>>>(w_ih2, G3*HO);
    gemm_bf16<HO><<<ggrid, 256, GEMM_SMEM>>>(b_ih2);
    gru7<<<64, 256>>>(w_hh2, b_hh2, out, seq, 2);
}

// round 15
// speedup vs baseline: 1.2403x; 1.2403x over previous
#include <cuda_runtime.h>
#include <cuda_bf16.h>
#include <mma.h>
#include <math.h>

using namespace nvcuda;

#define BB   32
#define TT   512
#define LAT  256
#define HID  1024
#define HO   512
#define G3   1536
#define MTOT (BB*TT)

// GRU partitioning: 4 independent groups x 8 batches, 32 CTAs per group.
#define NG   4
#define CPG  32
#define BPG  8
#define JPC  16
#define GROWS 48
#define RROW 10
#define RMT  160

#define GTLDA 40         // fp32 elems per smem row in tf32 gemm (32 data + 8 pad)

// ---------------- scratch (device globals; no allocations allowed) ----------
__device__ float g_fc[BB*HID];
__device__ float g_gx[(size_t)MTOT*G3];
__device__ float g_x0[(size_t)MTOT*HID];            // layer-0 GEMM A operand (fp32)
__device__ float g_y0[(size_t)MTOT*HO];             // layer-0 output (fp32)
__device__ float g_y1[(size_t)MTOT*HO];             // layer-1 output (fp32)
// stamped hidden state: low 32 = packed bf16 (hi | lo<<16), high 32 = stamp
__device__ unsigned long long g_hs[NG][2][BPG*HO];
__device__ unsigned int g_epoch[NG][CPG][8];        // per-CTA stamp base, padded

// fast gates (MUFU): rel err ~1e-6, budget 1e-3
__device__ __forceinline__ float sigf(float x) {
    return __fdividef(1.0f, 1.0f + __expf(-x));
}
__device__ __forceinline__ float tanhfast(float x) {
    return 2.0f * __fdividef(1.0f, 1.0f + __expf(-2.0f * x)) - 1.0f;
}

__device__ __forceinline__ void split1(float x, __nv_bfloat16& hi, __nv_bfloat16& lo) {
    hi = __float2bfloat16(x);
    lo = __float2bfloat16(x - __bfloat162float(hi));
}
__device__ __forceinline__ void split2(float x, float y, unsigned& hi, unsigned& lo) {
    __nv_bfloat16 hx, lx, hy, ly;
    split1(x, hx, lx); split1(y, hy, ly);
    __nv_bfloat162 h2 = __halves2bfloat162(hx, hy);
    __nv_bfloat162 l2 = __halves2bfloat162(lx, ly);
    hi = *reinterpret_cast<unsigned*>(&h2);
    lo = *reinterpret_cast<unsigned*>(&l2);
}
__device__ __forceinline__ unsigned prmtb(unsigned a, unsigned b, unsigned sel) {
    unsigned d;
    asm("prmt.b32 %0, %1, %2, %3;" : "=r"(d) : "r"(a), "r"(b), "r"(sel));
    return d;
}

// mma.m16n8k16 row.col f32 += bf16 * bf16
__device__ __forceinline__ void mma_bf16(float d[4], const unsigned a[4],
                                         unsigned b0, unsigned b1) {
    asm volatile(
        "mma.sync.aligned.m16n8k16.row.col.f32.bf16.bf16.f32 "
        "{%0,%1,%2,%3}, {%4,%5,%6,%7}, {%8,%9}, {%0,%1,%2,%3};"
        : "+f"(d[0]), "+f"(d[1]), "+f"(d[2]), "+f"(d[3])
        : "r"(a[0]), "r"(a[1]), "r"(a[2]), "r"(a[3]), "r"(b0), "r"(b1));
}

// ---------------- FC + ReLU --------------------------------------------------
__global__ void fc_kernel(const float* __restrict__ z,
                          const float* __restrict__ fc_w,
                          const float* __restrict__ fc_b) {
    __shared__ float zs[LAT];
    int b = blockIdx.x;
    zs[threadIdx.x] = z[b*LAT + threadIdx.x];
    __syncthreads();
    for (int h = threadIdx.x; h < HID; h += blockDim.x) {
        const float4* w = (const float4*)(fc_w + (size_t)h*LAT);
        float s = fc_b[h];
        #pragma unroll 8
        for (int k = 0; k < LAT/4; k++) {
            float4 wv = w[k];
            float4 zv = *(const float4*)(zs + 4*k);
            s += wv.x*zv.x + wv.y*zv.y + wv.z*zv.z + wv.w*zv.w;
        }
        g_fc[b*HID + h] = fmaxf(s, 0.0f);
    }
}

// ---------------- layer-0 A prepass: x0 = relu(fc)[b] + 0.01*chord (fp32) ----
__global__ void prep_a0(const float* __restrict__ chord) {
    size_t i = ((size_t)blockIdx.x*256 + threadIdx.x)*4;
    int m = (int)(i >> 10);
    int k = (int)(i & (HID-1));
    int b = m >> 9;
    float4 f = *(const float4*)(g_fc + (size_t)b*HID + k);
    float4 c = *(const float4*)(chord + i);
    float4 o = make_float4(f.x + 0.01f*c.x, f.y + 0.01f*c.y,
                           f.z + 0.01f*c.z, f.w + 0.01f*c.w);
    *(float4*)(g_x0 + i) = o;
}

// ---------------- Input projection GEMM: single-pass TF32 wmma ---------------
// g_gx[m][n] = sum_k A[m][k]*W[n][k] + bias[n]. A,W fp32 in gmem; cp.async to
// smem; wmma m16n16k8 tf32 (1 pass at rate/2 beats 3x bf16 passes at rate/3).
// 128m x 128n tile, k-step 32, double-buffered; 8 warps (32m x 64n each).
template<int K, int MODE>
__global__ void __launch_bounds__(256, 2) gemm_tf32(const float* __restrict__ W,
                                                    const float* __restrict__ bias) {
    extern __shared__ __align__(16) float ts[];   // [2][2][128][GTLDA]
    const float* A = (MODE == 0) ? g_x0 : (MODE == 1) ? g_y0 : g_y1;
    int bm = blockIdx.y*128, bn = blockIdx.x*128;
    int tid = threadIdx.x, lane = tid & 31, wid = tid >> 5;
    int wm = wid >> 1, wn = wid & 1;

    unsigned sb = (unsigned)__cvta_generic_to_shared(ts);

    // 2048 16B chunks: op 0 = A rows, op 1 = W rows; 8 chunks (128B) per row
    auto issue_stage = [&](int k0, int buf) {
        #pragma unroll
        for (int c = 0; c < 8; c++) {
            int chunk = tid + c*256;
            int op = chunk >> 10;
            int r = (chunk >> 3) & 127;
            int seg = chunk & 7;
            const float* gp = (op == 0)
                ? A + (size_t)(bm + r)*K + k0 + seg*4
                : W + (size_t)(bn + r)*K + k0 + seg*4;
            unsigned dst = sb + (((buf*2 + op)*128 + r)*GTLDA + seg*4)*4;
            asm volatile("cp.async.cg.shared.global [%0], [%1], 16;"
                         :: "r"(dst), "l"(gp));
        }
        asm volatile("cp.async.commit_group;");
    };
    auto plane = [&](int buf, int op) -> const float* {
        return ts + (size_t)((buf*2 + op)*128)*GTLDA;
    };

    wmma::fragment<wmma::accumulator,16,16,8,float> acc[2][4];
    #pragma unroll
    for (int i = 0; i < 2; i++)
        #pragma unroll
        for (int j = 0; j < 4; j++) wmma::fill_fragment(acc[i][j], 0.0f);

    issue_stage(0, 0);
    int buf = 0;
    constexpr int S = K/32;
    for (int s = 0; s < S; s++) {
        if (s + 1 < S) {
            issue_stage((s+1)*32, buf ^ 1);
            asm volatile("cp.async.wait_group 1;");
        } else {
            asm volatile("cp.async.wait_group 0;");
        }
        __syncthreads();
        #pragma unroll
        for (int kk = 0; kk < 32; kk += 8) {
            wmma::fragment<wmma::matrix_a,16,16,8,wmma::precision::tf32,wmma::row_major> fa[2];
            #pragma unroll
            for (int i = 0; i < 2; i++) {
                wmma::load_matrix_sync(fa[i], plane(buf,0) + (wm*32 + i*16)*GTLDA + kk, GTLDA);
                #pragma unroll
                for (int e = 0; e < fa[i].num_elements; e++)
                    fa[i].x[e] = wmma::__float_to_tf32(fa[i].x[e]);
            }
            #pragma unroll
            for (int j = 0; j < 4; j++) {
                wmma::fragment<wmma::matrix_b,16,16,8,wmma::precision::tf32,wmma::col_major> fb;
                wmma::load_matrix_sync(fb, plane(buf,1) + (wn*64 + j*16)*GTLDA + kk, GTLDA);
                #pragma unroll
                for (int e = 0; e < fb.num_elements; e++)
                    fb.x[e] = wmma::__float_to_tf32(fb.x[e]);
                #pragma unroll
                for (int i = 0; i < 2; i++)
                    wmma::mma_sync(acc[i][j], fa[i], fb, acc[i][j]);
            }
        }
        __syncthreads();
        buf ^= 1;
    }

    // epilogue: reuse ts as fp32 scratch (16x20 per warp)
    float* scratch = ts + wid*320;
    #pragma unroll
    for (int i = 0; i < 2; i++)
        #pragma unroll
        for (int j = 0; j < 4; j++) {
            wmma::store_matrix_sync(scratch, acc[i][j], 20, wmma::mem_row_major);
            __syncwarp();
            int r = lane >> 1, cb = (lane & 1)*8;
            int row = bm + wm*32 + i*16 + r;
            int col = bn + wn*64 + j*16 + cb;
            float4 v0 = *(float4*)&scratch[r*20 + cb];
            float4 v1 = *(float4*)&scratch[r*20 + cb + 4];
            const float* bp = bias + col;
            float* gp = g_gx + (size_t)row*G3 + col;
            *(float4*)gp = make_float4(v0.x + bp[0], v0.y + bp[1], v0.z + bp[2], v0.w + bp[3]);
            *(float4*)(gp + 4) = make_float4(v1.x + bp[4], v1.y + bp[5], v1.z + bp[6], v1.w + bp[7]);
            __syncwarp();
        }
}

// ---------------- Persistent GRU: stamped-data exchange (R12, proven) --------
// h published as one 8B word {packed bf16 hi|lo<<16, stamp = base+t}. 8B-aligned
// stores/loads are HW-atomic, so a stamp match certifies the h value in the same
// word -> consumers poll the data directly (ONE L2 trip). Buffer WAR and red[]
// double-buffering arguments as in R12. y stored as plain fp32 (tf32 GEMM input).
__global__ void __launch_bounds__(256) gru6(const float* __restrict__ whh,
                                            const float* __restrict__ bhh,
                                            float* __restrict__ dout,
                                            const int* __restrict__ seq_lens,
                                            int dst_mode) {
    __shared__ float red[2][24*RMT];
    __shared__ float bh_sm[GROWS];

    int tid = threadIdx.x, lane = tid & 31, warp = tid >> 5;
    int grp = blockIdx.x >> 5;
    int cig = blockIdx.x & 31;
    int jbase = cig * JPC;

    float* y = (dst_mode == 0) ? g_y0 : (dst_mode == 1) ? g_y1 : dout;

    unsigned base = g_epoch[grp][cig][0];

    // preload W fragments into registers (split-bf16 hi/lo)
    unsigned awhi[3][4][4], awlo[3][4][4];
    {
        int r = lane >> 2, c = (lane & 3)*2;
        #pragma unroll
        for (int m = 0; m < 3; m++) {
            size_t row0 = (size_t)(m*HO + jbase + r)*HO;
            size_t row1 = row0 + 8*(size_t)HO;
            #pragma unroll
            for (int kt4 = 0; kt4 < 4; kt4++) {
                int kb = (warp*4 + kt4)*16 + c;
                float2 w00 = *(const float2*)(whh + row0 + kb);
                float2 w10 = *(const float2*)(whh + row1 + kb);
                float2 w01 = *(const float2*)(whh + row0 + kb + 8);
                float2 w11 = *(const float2*)(whh + row1 + kb + 8);
                split2(w00.x, w00.y, awhi[m][kt4][0], awlo[m][kt4][0]);
                split2(w10.x, w10.y, awhi[m][kt4][1], awlo[m][kt4][1]);
                split2(w01.x, w01.y, awhi[m][kt4][2], awlo[m][kt4][2]);
                split2(w11.x, w11.y, awhi[m][kt4][3], awlo[m][kt4][3]);
            }
        }
    }
    if (tid < GROWS) bh_sm[tid] = bhh[(tid >> 4)*HO + jbase + (tid & 15)];

    const int gjj = tid & 15, gb = tid >> 4;
    const int b_glob = grp*BPG + gb;
    int slen = TT;
    if (dst_mode == 2 && tid < 128) slen = seq_lens[b_glob];

    float gxr = 0.f, gxz = 0.f, gxn = 0.f;
    if (tid < 128) {
        size_t bse = (size_t)b_glob*TT*G3 + jbase + gjj;
        gxr = g_gx[bse];
        gxz = g_gx[bse + HO];
        gxn = g_gx[bse + 2*HO];
    }
    float h_prev = 0.0f;
    __syncthreads();

    const int bq = lane >> 2;             // B-frag batch index
    const int kc2 = (lane & 3)*2;         // B-frag k offset

    for (int t = 0; t < TT; t++) {
        // ---- obtain h(t): poll stamped words (t>0) or zeros ----
        unsigned long long w[4][4];
        if (t == 0) {
            #pragma unroll
            for (int a = 0; a < 4; a++)
                #pragma unroll
                for (int e = 0; e < 4; e++) w[a][e] = 0ull;
        } else {
            const unsigned tgt = base + (unsigned)t;
            const unsigned long long* hb = g_hs[grp][t & 1] + bq*HO;
            bool ok;
            do {
                ok = true;
                #pragma unroll
                for (int kt4 = 0; kt4 < 4; kt4++) {
                    int kb = (warp*4 + kt4)*16 + kc2;
                    const unsigned long long* p = hb + kb;
                    asm volatile("ld.relaxed.gpu.global.u64 %0, [%1];" : "=l"(w[kt4][0]) : "l"(p));
                    asm volatile("ld.relaxed.gpu.global.u64 %0, [%1];" : "=l"(w[kt4][1]) : "l"(p + 1));
                    asm volatile("ld.relaxed.gpu.global.u64 %0, [%1];" : "=l"(w[kt4][2]) : "l"(p + 8));
                    asm volatile("ld.relaxed.gpu.global.u64 %0, [%1];" : "=l"(w[kt4][3]) : "l"(p + 9));
                    #pragma unroll
                    for (int e = 0; e < 4; e++)
                        ok &= ((unsigned)(w[kt4][e] >> 32) == tgt);
                }
            } while (__ballot_sync(0xffffffffu, !ok));
        }

        // ---- tensor-core GEMV (PRMT unpack of pre-split words) ----
        float d[3][4];
        #pragma unroll
        for (int m = 0; m < 3; m++)
            #pragma unroll
            for (int e = 0; e < 4; e++) d[m][e] = 0.0f;

        #pragma unroll
        for (int kt4 = 0; kt4 < 4; kt4++) {
            unsigned p0 = (unsigned)w[kt4][0], p1 = (unsigned)w[kt4][1];
            unsigned p2 = (unsigned)w[kt4][2], p3 = (unsigned)w[kt4][3];
            unsigned bh0 = prmtb(p0, p1, 0x5410), bl0 = prmtb(p0, p1, 0x7632);
            unsigned bh1 = prmtb(p2, p3, 0x5410), bl1 = prmtb(p2, p3, 0x7632);
            #pragma unroll
            for (int m = 0; m < 3; m++) {
                mma_bf16(d[m], awhi[m][kt4], bh0, bh1);
                mma_bf16(d[m], awhi[m][kt4], bl0, bl1);
                mma_bf16(d[m], awlo[m][kt4], bh0, bh1);
            }
        }
        {
            float* rb = red[t & 1];
            #pragma unroll
            for (int m = 0; m < 3; m++) {
                float* rp = rb + (warp*3 + m)*RMT + (lane>>2)*RROW + (lane&3)*2;
                *(float2*)rp            = make_float2(d[m][0], d[m][1]);
                *(float2*)(rp + 8*RROW) = make_float2(d[m][2], d[m][3]);
            }
        }
        __syncthreads();

        // ---- fused reduce + gate math + publish (tid<128) ----
        if (tid < 128) {
            const float* rb = red[t & 1];
            float gh[3];
            #pragma unroll
            for (int g = 0; g < 3; g++) {
                const float* rp = rb + g*RMT + gjj*RROW + gb;
                float s = 0.0f;
                #pragma unroll
                for (int w8 = 0; w8 < 8; w8++)
                    s += rp[w8*3*RMT];
                gh[g] = s + bh_sm[g*16 + gjj];
            }
            float r  = sigf(gxr + gh[0]);
            float zg = sigf(gxz + gh[1]);
            float n  = tanhfast(gxn + r*gh[2]);
            float hn2 = (1.0f - zg)*n + zg*h_prev;
            h_prev = hn2;

            if (t < TT - 1) {
                // publish FIRST (critical path for the whole group)
                __nv_bfloat16 hi, lo;
                split1(hn2, hi, lo);
                unsigned pk = (unsigned)*reinterpret_cast<unsigned short*>(&hi)
                            | ((unsigned)*reinterpret_cast<unsigned short*>(&lo) << 16);
                unsigned long long word =
                    ((unsigned long long)(base + (unsigned)(t + 1)) << 32) | pk;
                unsigned long long* hp = &g_hs[grp][(t + 1) & 1][gb*HO + jbase + gjj];
                asm volatile("st.relaxed.gpu.global.u64 [%0], %1;" :: "l"(hp), "l"(word));
            }
            // off-path: fp32 y store + gx(t+1) prefetch
            size_t idx = ((size_t)b_glob*TT + t)*HO + jbase + gjj;
            y[idx] = (dst_mode == 2 && t >= slen) ? 0.0f : hn2;
            if (t < TT - 1) {
                size_t bse = ((size_t)b_glob*TT + (t + 1))*G3 + jbase + gjj;
                gxr = g_gx[bse];
                gxz = g_gx[bse + HO];
                gxn = g_gx[bse + 2*HO];
            }
        }
        // no trailing sync: red double-buffered (see R12 argument)
    }
    if (tid == 0) g_epoch[grp][cig][0] = base + TT;
}

// ---------------- launch ----------------------------------------------------
#define GEMM_SMEM (2*2*128*GTLDA*4)

extern "C" void kernel_launch(void* const* d_in, const int* in_sizes, int n_in,
                              void* d_out, int out_size) {
    const float* z     = (const float*)d_in[0];
    const int*   seq   = (const int*)  d_in[1];
    const float* chord = (const float*)d_in[2];
    const float* fc_w  = (const float*)d_in[3];
    const float* fc_b  = (const float*)d_in[4];
    const float* w_ih0 = (const float*)d_in[5];
    const float* w_hh0 = (const float*)d_in[6];
    const float* b_ih0 = (const float*)d_in[7];
    const float* b_hh0 = (const float*)d_in[8];
    const float* w_ih1 = (const float*)d_in[9];
    const float* w_hh1 = (const float*)d_in[10];
    const float* b_ih1 = (const float*)d_in[11];
    const float* b_hh1 = (const float*)d_in[12];
    const float* w_ih2 = (const float*)d_in[13];
    const float* w_hh2 = (const float*)d_in[14];
    const float* b_ih2 = (const float*)d_in[15];
    const float* b_hh2 = (const float*)d_in[16];
    float* out = (float*)d_out;

    cudaFuncSetAttribute(gemm_tf32<HID,0>, cudaFuncAttributeMaxDynamicSharedMemorySize, GEMM_SMEM);
    cudaFuncSetAttribute(gemm_tf32<HO,1>,  cudaFuncAttributeMaxDynamicSharedMemorySize, GEMM_SMEM);
    cudaFuncSetAttribute(gemm_tf32<HO,2>,  cudaFuncAttributeMaxDynamicSharedMemorySize, GEMM_SMEM);

    dim3 ggrid(G3/128, MTOT/128);   // (12, 128)

    fc_kernel<<<BB, LAT>>>(z, fc_w, fc_b);
    prep_a0<<<(int)(((size_t)MTOT*HID)/1024), 256>>>(chord);

    gemm_tf32<HID,0><<<ggrid, 256, GEMM_SMEM>>>(w_ih0, b_ih0);
    gru6<<<NG*CPG, 256>>>(w_hh0, b_hh0, nullptr, seq, 0);

    gemm_tf32<HO,1><<<ggrid, 256, GEMM_SMEM>>>(w_ih1, b_ih1);
    gru6<<<NG*CPG, 256>>>(w_hh1, b_hh1, nullptr, seq, 1);

    gemm_tf32<HO,2><<<ggrid, 256, GEMM_SMEM>>>(w_ih2, b_ih2);
    gru6<<<NG*CPG, 256>>>(w_hh2, b_hh2, out, seq, 2);
}

// round 16
// speedup vs baseline: 1.4374x; 1.1589x over previous
#include <cuda_runtime.h>
#include <cuda_bf16.h>
#include <mma.h>
#include <math.h>

using namespace nvcuda;

#define BB   32
#define TT   512
#define LAT  256
#define HID  1024
#define HO   512
#define G3   1536
#define MTOT (BB*TT)

// GRU partitioning: 4 independent groups x 8 batches, 32 CTAs per group.
#define NG   4
#define CPG  32
#define BPG  8
#define JPC  16
#define GROWS 48
#define RROW 10
#define RMT  160

#define GLDA 40          // bf16 elems per smem row in gemm (32 data + 8 pad = 80B)

// ---------------- scratch (device globals; no allocations allowed) ----------
__device__ float g_fc[BB*HID];
__device__ float g_gx[(size_t)MTOT*G3];
__device__ __nv_bfloat16 g_ahi[(size_t)MTOT*HID];   // A operand hi
__device__ __nv_bfloat16 g_alo[(size_t)MTOT*HID];   // A operand lo
__device__ __nv_bfloat16 g_whi[(size_t)G3*HID];     // W operand hi (re-split per layer)
__device__ __nv_bfloat16 g_wlo[(size_t)G3*HID];
// stamped hidden state: low 32 = packed bf16 (hi | lo<<16), high 32 = stamp
__device__ unsigned long long g_hs[NG][2][BPG*HO];
__device__ unsigned int g_epoch[NG][CPG][8];        // per-CTA stamp base, padded

// fast gates (MUFU): rel err ~1e-6, budget 1e-3
__device__ __forceinline__ float sigf(float x) {
    return __fdividef(1.0f, 1.0f + __expf(-x));
}
__device__ __forceinline__ float tanhfast(float x) {
    return 2.0f * __fdividef(1.0f, 1.0f + __expf(-2.0f * x)) - 1.0f;
}

__device__ __forceinline__ void split1(float x, __nv_bfloat16& hi, __nv_bfloat16& lo) {
    hi = __float2bfloat16(x);
    lo = __float2bfloat16(x - __bfloat162float(hi));
}
__device__ __forceinline__ void split2(float x, float y, unsigned& hi, unsigned& lo) {
    __nv_bfloat16 hx, lx, hy, ly;
    split1(x, hx, lx); split1(y, hy, ly);
    __nv_bfloat162 h2 = __halves2bfloat162(hx, hy);
    __nv_bfloat162 l2 = __halves2bfloat162(lx, ly);
    hi = *reinterpret_cast<unsigned*>(&h2);
    lo = *reinterpret_cast<unsigned*>(&l2);
}
__device__ __forceinline__ unsigned prmtb(unsigned a, unsigned b, unsigned sel) {
    unsigned d;
    asm("prmt.b32 %0, %1, %2, %3;" : "=r"(d) : "r"(a), "r"(b), "r"(sel));
    return d;
}

// mma.m16n8k16 row.col f32 += bf16 * bf16
__device__ __forceinline__ void mma_bf16(float d[4], const unsigned a[4],
                                         unsigned b0, unsigned b1) {
    asm volatile(
        "mma.sync.aligned.m16n8k16.row.col.f32.bf16.bf16.f32 "
        "{%0,%1,%2,%3}, {%4,%5,%6,%7}, {%8,%9}, {%0,%1,%2,%3};"
        : "+f"(d[0]), "+f"(d[1]), "+f"(d[2]), "+f"(d[3])
        : "r"(a[0]), "r"(a[1]), "r"(a[2]), "r"(a[3]), "r"(b0), "r"(b1));
}

// ---------------- FC + ReLU --------------------------------------------------
__global__ void fc_kernel(const float* __restrict__ z,
                          const float* __restrict__ fc_w,
                          const float* __restrict__ fc_b) {
    __shared__ float zs[LAT];
    int b = blockIdx.x;
    zs[threadIdx.x] = z[b*LAT + threadIdx.x];
    __syncthreads();
    for (int h = threadIdx.x; h < HID; h += blockDim.x) {
        const float4* w = (const float4*)(fc_w + (size_t)h*LAT);
        float s = fc_b[h];
        #pragma unroll 8
        for (int k = 0; k < LAT/4; k++) {
            float4 wv = w[k];
            float4 zv = *(const float4*)(zs + 4*k);
            s += wv.x*zv.x + wv.y*zv.y + wv.z*zv.z + wv.w*zv.w;
        }
        g_fc[b*HID + h] = fmaxf(s, 0.0f);
    }
}

// ---------------- split prepasses -------------------------------------------
__global__ void split_w(const float* __restrict__ W, int n) {
    int i = (blockIdx.x*256 + threadIdx.x)*4;
    if (i >= n) return;
    float4 v = *(const float4*)(W + i);
    __nv_bfloat16 h0,l0,h1,l1,h2,l2,h3,l3;
    split1(v.x,h0,l0); split1(v.y,h1,l1); split1(v.z,h2,l2); split1(v.w,h3,l3);
    *(__nv_bfloat162*)(g_whi + i)     = __halves2bfloat162(h0,h1);
    *(__nv_bfloat162*)(g_whi + i + 2) = __halves2bfloat162(h2,h3);
    *(__nv_bfloat162*)(g_wlo + i)     = __halves2bfloat162(l0,l1);
    *(__nv_bfloat162*)(g_wlo + i + 2) = __halves2bfloat162(l2,l3);
}

__global__ void split_a0(const float* __restrict__ chord) {
    size_t i = ((size_t)blockIdx.x*256 + threadIdx.x)*4;
    int m = (int)(i >> 10);
    int k = (int)(i & (HID-1));
    int b = m >> 9;
    float4 f = *(const float4*)(g_fc + (size_t)b*HID + k);
    float4 c = *(const float4*)(chord + i);
    float a0 = f.x + 0.01f*c.x, a1 = f.y + 0.01f*c.y;
    float a2 = f.z + 0.01f*c.z, a3 = f.w + 0.01f*c.w;
    __nv_bfloat16 h0,l0,h1,l1,h2,l2,h3,l3;
    split1(a0,h0,l0); split1(a1,h1,l1); split1(a2,h2,l2); split1(a3,h3,l3);
    *(__nv_bfloat162*)(g_ahi + i)     = __halves2bfloat162(h0,h1);
    *(__nv_bfloat162*)(g_ahi + i + 2) = __halves2bfloat162(h2,h3);
    *(__nv_bfloat162*)(g_alo + i)     = __halves2bfloat162(l0,l1);
    *(__nv_bfloat162*)(g_alo + i + 2) = __halves2bfloat162(l2,l3);
}

// ---------------- Input projection GEMM: pre-split bf16, cp.async, wmma ------
// (R11/R12 128x128 config, proven 493us for K=1024)
template<int K>
__global__ void __launch_bounds__(256, 2) gemm_bf16(const float* __restrict__ bias) {
    extern __shared__ __align__(16) __nv_bfloat16 ts[];   // [2][4][128][GLDA]
    int bm = blockIdx.y*128, bn = blockIdx.x*128;
    int tid = threadIdx.x, lane = tid & 31, wid = tid >> 5;
    int wm = wid >> 1, wn = wid & 1;

    unsigned sb = (unsigned)__cvta_generic_to_shared(ts);

    auto issue_stage = [&](int k0, int buf) {
        #pragma unroll
        for (int c = 0; c < 8; c++) {
            int chunk = tid + c*256;
            int op = chunk >> 9;
            int r = (chunk >> 2) & 127;
            int seg = chunk & 3;
            const __nv_bfloat16* gp;
            if (op == 0)      gp = g_ahi + (size_t)(bm + r)*K + k0 + seg*8;
            else if (op == 1) gp = g_alo + (size_t)(bm + r)*K + k0 + seg*8;
            else if (op == 2) gp = g_whi + (size_t)(bn + r)*K + k0 + seg*8;
            else              gp = g_wlo + (size_t)(bn + r)*K + k0 + seg*8;
            unsigned dst = sb + (((buf*4 + op)*128 + r)*GLDA + seg*8)*2;
            asm volatile("cp.async.cg.shared.global [%0], [%1], 16;"
                         :: "r"(dst), "l"(gp));
        }
        asm volatile("cp.async.commit_group;");
    };
    auto plane = [&](int buf, int op) -> const __nv_bfloat16* {
        return ts + (size_t)((buf*4 + op)*128)*GLDA;
    };

    wmma::fragment<wmma::accumulator,16,16,16,float> acc[2][4];
    #pragma unroll
    for (int i = 0; i < 2; i++)
        #pragma unroll
        for (int j = 0; j < 4; j++) wmma::fill_fragment(acc[i][j], 0.0f);

    issue_stage(0, 0);
    int buf = 0;
    constexpr int S = K/32;
    for (int s = 0; s < S; s++) {
        if (s + 1 < S) {
            issue_stage((s+1)*32, buf ^ 1);
            asm volatile("cp.async.wait_group 1;");
        } else {
            asm volatile("cp.async.wait_group 0;");
        }
        __syncthreads();
        #pragma unroll
        for (int kk = 0; kk < 32; kk += 16) {
            wmma::fragment<wmma::matrix_a,16,16,16,__nv_bfloat16,wmma::row_major> fa_h[2], fa_l[2];
            #pragma unroll
            for (int i = 0; i < 2; i++) {
                wmma::load_matrix_sync(fa_h[i], plane(buf,0) + (wm*32 + i*16)*GLDA + kk, GLDA);
                wmma::load_matrix_sync(fa_l[i], plane(buf,1) + (wm*32 + i*16)*GLDA + kk, GLDA);
            }
            #pragma unroll
            for (int j = 0; j < 4; j++) {
                wmma::fragment<wmma::matrix_b,16,16,16,__nv_bfloat16,wmma::col_major> fb_h, fb_l;
                wmma::load_matrix_sync(fb_h, plane(buf,2) + (wn*64 + j*16)*GLDA + kk, GLDA);
                wmma::load_matrix_sync(fb_l, plane(buf,3) + (wn*64 + j*16)*GLDA + kk, GLDA);
                #pragma unroll
                for (int i = 0; i < 2; i++) {
                    wmma::mma_sync(acc[i][j], fa_h[i], fb_h, acc[i][j]);
                    wmma::mma_sync(acc[i][j], fa_h[i], fb_l, acc[i][j]);
                    wmma::mma_sync(acc[i][j], fa_l[i], fb_h, acc[i][j]);
                }
            }
        }
        __syncthreads();
        buf ^= 1;
    }

    float* scratch = reinterpret_cast<float*>(ts) + wid*320;
    #pragma unroll
    for (int i = 0; i < 2; i++)
        #pragma unroll
        for (int j = 0; j < 4; j++) {
            wmma::store_matrix_sync(scratch, acc[i][j], 20, wmma::mem_row_major);
            __syncwarp();
            int r = lane >> 1, cb = (lane & 1)*8;
            int row = bm + wm*32 + i*16 + r;
            int col = bn + wn*64 + j*16 + cb;
            float4 v0 = *(float4*)&scratch[r*20 + cb];
            float4 v1 = *(float4*)&scratch[r*20 + cb + 4];
            const float* bp = bias + col;
            float* gp = g_gx + (size_t)row*G3 + col;
            *(float4*)gp = make_float4(v0.x + bp[0], v0.y + bp[1], v0.z + bp[2], v0.w + bp[3]);
            *(float4*)(gp + 4) = make_float4(v1.x + bp[4], v1.y + bp[5], v1.z + bp[6], v1.w + bp[7]);
            __syncwarp();
        }
}

// ---------------- Persistent GRU: stamped-data exchange (R12, proven) --------
// h published as one 8B word {packed bf16 hi|lo<<16, stamp = base+t}. 8B-aligned
// stores/loads are HW-atomic, so a stamp match certifies the h value in the same
// word -> consumers poll the data directly (ONE L2 trip; no flags, no 2nd LDG).
// Buffer WAR safety: CTA A writes buf[(t+1)&1] at gate(t) only after A's warps
// consumed stamps==t for ALL 32 producers; producer B stamped h(t) only after
// B's GEMV(t-1) reads of buf[(t-1)&1] completed (values already in regs). So
// A's write happens-after every read of that buffer parity. red[] is double-
// buffered -> ONE __syncthreads per step.
// R15 micro: gx(t+1) loads issued BEFORE the y/ahi/alo stores (loads on the
// next iteration's dependency path go first in the LSU queue).
__global__ void __launch_bounds__(256) gru6(const float* __restrict__ whh,
                                            const float* __restrict__ bhh,
                                            float* __restrict__ dout,
                                            const int* __restrict__ seq_lens,
                                            int dst_mode) {
    __shared__ float red[2][24*RMT];
    __shared__ float bh_sm[GROWS];

    int tid = threadIdx.x, lane = tid & 31, warp = tid >> 5;
    int grp = blockIdx.x >> 5;
    int cig = blockIdx.x & 31;
    int jbase = cig * JPC;

    unsigned base = g_epoch[grp][cig][0];

    // preload W fragments into registers (split-bf16 hi/lo)
    unsigned awhi[3][4][4], awlo[3][4][4];
    {
        int r = lane >> 2, c = (lane & 3)*2;
        #pragma unroll
        for (int m = 0; m < 3; m++) {
            size_t row0 = (size_t)(m*HO + jbase + r)*HO;
            size_t row1 = row0 + 8*(size_t)HO;
            #pragma unroll
            for (int kt4 = 0; kt4 < 4; kt4++) {
                int kb = (warp*4 + kt4)*16 + c;
                float2 w00 = *(const float2*)(whh + row0 + kb);
                float2 w10 = *(const float2*)(whh + row1 + kb);
                float2 w01 = *(const float2*)(whh + row0 + kb + 8);
                float2 w11 = *(const float2*)(whh + row1 + kb + 8);
                split2(w00.x, w00.y, awhi[m][kt4][0], awlo[m][kt4][0]);
                split2(w10.x, w10.y, awhi[m][kt4][1], awlo[m][kt4][1]);
                split2(w01.x, w01.y, awhi[m][kt4][2], awlo[m][kt4][2]);
                split2(w11.x, w11.y, awhi[m][kt4][3], awlo[m][kt4][3]);
            }
        }
    }
    if (tid < GROWS) bh_sm[tid] = bhh[(tid >> 4)*HO + jbase + (tid & 15)];

    const int gjj = tid & 15, gb = tid >> 4;
    const int b_glob = grp*BPG + gb;
    int slen = TT;
    if (dst_mode == 2 && tid < 128) slen = seq_lens[b_glob];

    float gxr = 0.f, gxz = 0.f, gxn = 0.f;
    if (tid < 128) {
        size_t bse = (size_t)b_glob*TT*G3 + jbase + gjj;
        gxr = g_gx[bse];
        gxz = g_gx[bse + HO];
        gxn = g_gx[bse + 2*HO];
    }
    float h_prev = 0.0f;
    __syncthreads();

    const int bq = lane >> 2;             // B-frag batch index
    const int kc2 = (lane & 3)*2;         // B-frag k offset

    for (int t = 0; t < TT; t++) {
        // ---- obtain h(t): poll stamped words (t>0) or zeros ----
        unsigned long long w[4][4];
        if (t == 0) {
            #pragma unroll
            for (int a = 0; a < 4; a++)
                #pragma unroll
                for (int e = 0; e < 4; e++) w[a][e] = 0ull;
        } else {
            const unsigned tgt = base + (unsigned)t;
            const unsigned long long* hb = g_hs[grp][t & 1] + bq*HO;
            bool ok;
            do {
                ok = true;
                #pragma unroll
                for (int kt4 = 0; kt4 < 4; kt4++) {
                    int kb = (warp*4 + kt4)*16 + kc2;
                    const unsigned long long* p = hb + kb;
                    asm volatile("ld.relaxed.gpu.global.u64 %0, [%1];" : "=l"(w[kt4][0]) : "l"(p));
                    asm volatile("ld.relaxed.gpu.global.u64 %0, [%1];" : "=l"(w[kt4][1]) : "l"(p + 1));
                    asm volatile("ld.relaxed.gpu.global.u64 %0, [%1];" : "=l"(w[kt4][2]) : "l"(p + 8));
                    asm volatile("ld.relaxed.gpu.global.u64 %0, [%1];" : "=l"(w[kt4][3]) : "l"(p + 9));
                    #pragma unroll
                    for (int e = 0; e < 4; e++)
                        ok &= ((unsigned)(w[kt4][e] >> 32) == tgt);
                }
            } while (__ballot_sync(0xffffffffu, !ok));
        }

        // ---- tensor-core GEMV (PRMT unpack of pre-split words) ----
        float d[3][4];
        #pragma unroll
        for (int m = 0; m < 3; m++)
            #pragma unroll
            for (int e = 0; e < 4; e++) d[m][e] = 0.0f;

        #pragma unroll
        for (int kt4 = 0; kt4 < 4; kt4++) {
            unsigned p0 = (unsigned)w[kt4][0], p1 = (unsigned)w[kt4][1];
            unsigned p2 = (unsigned)w[kt4][2], p3 = (unsigned)w[kt4][3];
            unsigned bh0 = prmtb(p0, p1, 0x5410), bl0 = prmtb(p0, p1, 0x7632);
            unsigned bh1 = prmtb(p2, p3, 0x5410), bl1 = prmtb(p2, p3, 0x7632);
            #pragma unroll
            for (int m = 0; m < 3; m++) {
                mma_bf16(d[m], awhi[m][kt4], bh0, bh1);
                mma_bf16(d[m], awhi[m][kt4], bl0, bl1);
                mma_bf16(d[m], awlo[m][kt4], bh0, bh1);
            }
        }
        {
            float* rb = red[t & 1];
            #pragma unroll
            for (int m = 0; m < 3; m++) {
                float* rp = rb + (warp*3 + m)*RMT + (lane>>2)*RROW + (lane&3)*2;
                *(float2*)rp            = make_float2(d[m][0], d[m][1]);
                *(float2*)(rp + 8*RROW) = make_float2(d[m][2], d[m][3]);
            }
        }
        __syncthreads();

        // ---- fused reduce + gate math + publish (tid<128) ----
        if (tid < 128) {
            const float* rb = red[t & 1];
            float gh[3];
            #pragma unroll
            for (int g = 0; g < 3; g++) {
                const float* rp = rb + g*RMT + gjj*RROW + gb;
                float s = 0.0f;
                #pragma unroll
                for (int w8 = 0; w8 < 8; w8++)
                    s += rp[w8*3*RMT];
                gh[g] = s + bh_sm[g*16 + gjj];
            }
            float r  = sigf(gxr + gh[0]);
            float zg = sigf(gxz + gh[1]);
            float n  = tanhfast(gxn + r*gh[2]);
            float hn2 = (1.0f - zg)*n + zg*h_prev;
            h_prev = hn2;

            __nv_bfloat16 hi, lo;
            split1(hn2, hi, lo);
            unsigned pk = (unsigned)*reinterpret_cast<unsigned short*>(&hi)
                        | ((unsigned)*reinterpret_cast<unsigned short*>(&lo) << 16);

            if (t < TT - 1) {
                // publish FIRST (critical path for the whole group)
                unsigned long long word =
                    ((unsigned long long)(base + (unsigned)(t + 1)) << 32) | pk;
                unsigned long long* hp = &g_hs[grp][(t + 1) & 1][gb*HO + jbase + gjj];
                asm volatile("st.relaxed.gpu.global.u64 [%0], %1;" :: "l"(hp), "l"(word));
                // then loads (next-iteration dependency path) ...
                size_t bse = ((size_t)b_glob*TT + (t + 1))*G3 + jbase + gjj;
                gxr = g_gx[bse];
                gxz = g_gx[bse + HO];
                gxn = g_gx[bse + 2*HO];
            }
            // ... then off-path stores
            size_t idx = ((size_t)b_glob*TT + t)*HO + jbase + gjj;
            if (dst_mode == 2) {
                dout[idx] = (t < slen) ? hn2 : 0.0f;
            } else {
                g_ahi[idx] = hi;
                g_alo[idx] = lo;
            }
        }
        // no trailing sync: red is double-buffered; cross-iter ordering is via
        // the single barrier (gate reads of red[t&1] precede sync(t+1), any
        // warp's next write of red[t&1] is at iter t+2, after sync(t+1)).
    }
    if (tid == 0) g_epoch[grp][cig][0] = base + TT;
}

// ---------------- launch ----------------------------------------------------
#define GEMM_SMEM (2*4*128*GLDA*2)

extern "C" void kernel_launch(void* const* d_in, const int* in_sizes, int n_in,
                              void* d_out, int out_size) {
    const float* z     = (const float*)d_in[0];
    const int*   seq   = (const int*)  d_in[1];
    const float* chord = (const float*)d_in[2];
    const float* fc_w  = (const float*)d_in[3];
    const float* fc_b  = (const float*)d_in[4];
    const float* w_ih0 = (const float*)d_in[5];
    const float* w_hh0 = (const float*)d_in[6];
    const float* b_ih0 = (const float*)d_in[7];
    const float* b_hh0 = (const float*)d_in[8];
    const float* w_ih1 = (const float*)d_in[9];
    const float* w_hh1 = (const float*)d_in[10];
    const float* b_ih1 = (const float*)d_in[11];
    const float* b_hh1 = (const float*)d_in[12];
    const float* w_ih2 = (const float*)d_in[13];
    const float* w_hh2 = (const float*)d_in[14];
    const float* b_ih2 = (const float*)d_in[15];
    const float* b_hh2 = (const float*)d_in[16];
    float* out = (float*)d_out;

    cudaFuncSetAttribute(gemm_bf16<HID>, cudaFuncAttributeMaxDynamicSharedMemorySize, GEMM_SMEM);
    cudaFuncSetAttribute(gemm_bf16<HO>,  cudaFuncAttributeMaxDynamicSharedMemorySize, GEMM_SMEM);

    dim3 ggrid(G3/128, MTOT/128);   // (12, 128)

    fc_kernel<<<BB, LAT>>>(z, fc_w, fc_b);
    split_a0<<<(int)(((size_t)MTOT*HID)/1024), 256>>>(chord);

    split_w<<<(G3*HID)/1024, 256>>>(w_ih0, G3*HID);
    gemm_bf16<HID><<<ggrid, 256, GEMM_SMEM>>>(b_ih0);
    gru6<<<NG*CPG, 256>>>(w_hh0, b_hh0, nullptr, seq, 0);

    split_w<<<(G3*HO)/1024, 256>>>(w_ih1, G3*HO);
    gemm_bf16<HO><<<ggrid, 256, GEMM_SMEM>>>(b_ih1);
    gru6<<<NG*CPG, 256>>>(w_hh1, b_hh1, nullptr, seq, 1);

    split_w<<<(G3*HO)/1024, 256>>>(w_ih2, G3*HO);
    gemm_bf16<HO><<<ggrid, 256, GEMM_SMEM>>>(b_ih2);
    gru6<<<NG*CPG, 256>>>(w_hh2, b_hh2, out, seq, 2);
}